// round 1
// baseline (speedup 1.0000x reference)
#include <cuda_runtime.h>
#include <cuda_bf16.h>
#include <cstddef>

// ---------------- problem constants ----------------
#define NPAR   4096
#define KCH    32
#define NEIGHD 128
#define FEATD  256
#define NROWS  (NPAR * KCH)        // 131072
#define H1D    512
#define H2D    512
#define H3D    256
#define INSTR  (NEIGHD + FEATD)    // 384 input row stride

// output layout: [relative_points (NROWS*3) | h (NROWS*256) | cluster (NROWS)]
#define RP_OFF 0
#define H_OFF  ((size_t)NROWS * 3)                 // 393216
#define CL_OFF (H_OFF + (size_t)NROWS * H3D)       // 33947648

// ---------------- scratch (device globals, no runtime alloc) ----------------
__device__ float g_F1[(size_t)NPAR * H1D];     // features @ W1[:256] + b1   (8 MB)
__device__ float g_H2[(size_t)NROWS * H2D];    // relu(h1 @ W2 + b2)         (256 MB)

// ---------------- kernel 1: decoder GEMM (relative_points) ----------------
// relative_points[p*96 + n] = sum_k neigh[p,k] * W_dec[k,n] + b_dec[n]
__global__ void k_dec(const float* __restrict__ inf, const float* __restrict__ Wd,
                      const float* __restrict__ bd, float* __restrict__ out_rp)
{
    __shared__ float s[NEIGHD];
    const int p = blockIdx.x;
    const int t = threadIdx.x;          // 128 threads
    s[t] = inf[(size_t)p * INSTR + t];
    __syncthreads();
    if (t < 96) {
        float acc = bd[t];
#pragma unroll 8
        for (int k = 0; k < NEIGHD; ++k)
            acc = fmaf(s[k], Wd[k * 96 + t], acc);
        out_rp[(size_t)p * 96 + t] = acc;
    }
}

// ---------------- kernel 2: cluster indices ----------------
__global__ void k_cluster(float* __restrict__ out_cl)
{
    const int i = blockIdx.x * blockDim.x + threadIdx.x;
    if (i < NROWS) out_cl[i] = (float)(i >> 5);
}

// =======================================================================
// Shared 128x128x16 fp32 GEMM skeleton: 256 threads, 8x8 microtile/thread.
// As stored transposed [k][m] with stride 132 (pad kills bank conflicts).
// =======================================================================

// ---------------- kernel 3: F1 = features @ W1[0:256,:] + b1 (no relu) ----
__global__ void k_f1(const float* __restrict__ inf, const float* __restrict__ W1,
                     const float* __restrict__ b1)
{
    __shared__ float As[16 * 132];
    __shared__ float Bs[16 * 128];
    const int tid  = threadIdx.x;
    const int bm   = blockIdx.x * 128;
    const int bn   = blockIdx.y * 128;
    const int arow = tid >> 2;           // 0..63
    const int acol = (tid & 3) * 4;      // 0,4,8,12
    const int brow = tid >> 5;           // 0..7
    const int bcol = (tid & 31) * 4;
    const int tr   = (tid >> 4) * 8;
    const int tc   = (tid & 15) * 8;

    float acc[8][8];
#pragma unroll
    for (int i = 0; i < 8; ++i)
#pragma unroll
        for (int j = 0; j < 8; ++j) acc[i][j] = 0.f;

    for (int kt = 0; kt < FEATD; kt += 16) {
#pragma unroll
        for (int s = 0; s < 2; ++s) {
            const int m = arow + s * 64;
            const float4 av = *(const float4*)&inf[(size_t)(bm + m) * INSTR + NEIGHD + kt + acol];
            As[(acol + 0) * 132 + m] = av.x;
            As[(acol + 1) * 132 + m] = av.y;
            As[(acol + 2) * 132 + m] = av.z;
            As[(acol + 3) * 132 + m] = av.w;
        }
#pragma unroll
        for (int s = 0; s < 2; ++s) {
            const int k = brow + s * 8;
            *(float4*)&Bs[k * 128 + bcol] =
                *(const float4*)&W1[(size_t)(kt + k) * H1D + bn + bcol];
        }
        __syncthreads();
#pragma unroll
        for (int k = 0; k < 16; ++k) {
            const float4 a0 = *(const float4*)&As[k * 132 + tr];
            const float4 a1 = *(const float4*)&As[k * 132 + tr + 4];
            const float4 b0 = *(const float4*)&Bs[k * 128 + tc];
            const float4 b1v = *(const float4*)&Bs[k * 128 + tc + 4];
            const float am[8] = {a0.x, a0.y, a0.z, a0.w, a1.x, a1.y, a1.z, a1.w};
            const float bnv[8] = {b0.x, b0.y, b0.z, b0.w, b1v.x, b1v.y, b1v.z, b1v.w};
#pragma unroll
            for (int i = 0; i < 8; ++i)
#pragma unroll
                for (int j = 0; j < 8; ++j)
                    acc[i][j] = fmaf(am[i], bnv[j], acc[i][j]);
        }
        __syncthreads();
    }
#pragma unroll
    for (int i = 0; i < 8; ++i) {
        const size_t row = (size_t)(bm + tr + i);
#pragma unroll
        for (int j = 0; j < 8; ++j)
            g_F1[row * H1D + bn + tc + j] = acc[i][j] + b1[bn + tc + j];
    }
}

// ---------------- kernel 4: fused h1-rebuild + L2 GEMM ----------------
// h1[r,k] = relu(F1[r>>5,k] + rp[r,0]*W1[256,k] + rp[r,1]*W1[257,k] + rp[r,2]*W1[258,k])
// g_H2 = relu(h1 @ W2 + b2)
__global__ void k_l2(const float* __restrict__ rp, const float* __restrict__ W1,
                     const float* __restrict__ W2, const float* __restrict__ b2)
{
    __shared__ float As[16 * 132];
    __shared__ float Bs[16 * 128];
    __shared__ float w1t[3 * H1D];     // W1 tail rows 256..258, full width
    __shared__ float rps[128 * 3];     // rel points for this row tile
    const int tid  = threadIdx.x;
    const int bm   = blockIdx.x * 128;
    const int bn   = blockIdx.y * 128;
    const int arow = tid >> 2;
    const int acol = (tid & 3) * 4;
    const int brow = tid >> 5;
    const int bcol = (tid & 31) * 4;
    const int tr   = (tid >> 4) * 8;
    const int tc   = (tid & 15) * 8;

    for (int i = tid; i < 3 * H1D; i += 256)
        w1t[i] = W1[(size_t)(FEATD + i / H1D) * H1D + (i % H1D)];
    for (int i = tid; i < 128 * 3; i += 256)
        rps[i] = rp[(size_t)bm * 3 + i];

    float acc[8][8];
#pragma unroll
    for (int i = 0; i < 8; ++i)
#pragma unroll
        for (int j = 0; j < 8; ++j) acc[i][j] = 0.f;

    __syncthreads();   // w1t / rps ready

    for (int kt = 0; kt < H1D; kt += 16) {
#pragma unroll
        for (int s = 0; s < 2; ++s) {
            const int m = arow + s * 64;
            const int parent = (bm + m) >> 5;
            const float r0 = rps[m * 3 + 0];
            const float r1 = rps[m * 3 + 1];
            const float r2 = rps[m * 3 + 2];
            const float4 fv = *(const float4*)&g_F1[(size_t)parent * H1D + kt + acol];
            const float4 wa = *(const float4*)&w1t[kt + acol];
            const float4 wb = *(const float4*)&w1t[H1D + kt + acol];
            const float4 wc = *(const float4*)&w1t[2 * H1D + kt + acol];
            As[(acol + 0) * 132 + m] = fmaxf(fv.x + r0 * wa.x + r1 * wb.x + r2 * wc.x, 0.f);
            As[(acol + 1) * 132 + m] = fmaxf(fv.y + r0 * wa.y + r1 * wb.y + r2 * wc.y, 0.f);
            As[(acol + 2) * 132 + m] = fmaxf(fv.z + r0 * wa.z + r1 * wb.z + r2 * wc.z, 0.f);
            As[(acol + 3) * 132 + m] = fmaxf(fv.w + r0 * wa.w + r1 * wb.w + r2 * wc.w, 0.f);
        }
#pragma unroll
        for (int s = 0; s < 2; ++s) {
            const int k = brow + s * 8;
            *(float4*)&Bs[k * 128 + bcol] =
                *(const float4*)&W2[(size_t)(kt + k) * H2D + bn + bcol];
        }
        __syncthreads();
#pragma unroll
        for (int k = 0; k < 16; ++k) {
            const float4 a0 = *(const float4*)&As[k * 132 + tr];
            const float4 a1 = *(const float4*)&As[k * 132 + tr + 4];
            const float4 b0 = *(const float4*)&Bs[k * 128 + tc];
            const float4 b1v = *(const float4*)&Bs[k * 128 + tc + 4];
            const float am[8] = {a0.x, a0.y, a0.z, a0.w, a1.x, a1.y, a1.z, a1.w};
            const float bnv[8] = {b0.x, b0.y, b0.z, b0.w, b1v.x, b1v.y, b1v.z, b1v.w};
#pragma unroll
            for (int i = 0; i < 8; ++i)
#pragma unroll
                for (int j = 0; j < 8; ++j)
                    acc[i][j] = fmaf(am[i], bnv[j], acc[i][j]);
        }
        __syncthreads();
    }
#pragma unroll
    for (int i = 0; i < 8; ++i) {
        const size_t row = (size_t)(bm + tr + i);
#pragma unroll
        for (int j = 0; j < 8; ++j)
            g_H2[row * H2D + bn + tc + j] = fmaxf(acc[i][j] + b2[bn + tc + j], 0.f);
    }
}

// ---------------- kernel 5: L3 GEMM -> output ----------------
// out_h = relu(g_H2 @ W3 + b3)
__global__ void k_l3(const float* __restrict__ W3, const float* __restrict__ b3,
                     float* __restrict__ outh)
{
    __shared__ float As[16 * 132];
    __shared__ float Bs[16 * 128];
    const int tid  = threadIdx.x;
    const int bm   = blockIdx.x * 128;
    const int bn   = blockIdx.y * 128;
    const int arow = tid >> 2;
    const int acol = (tid & 3) * 4;
    const int brow = tid >> 5;
    const int bcol = (tid & 31) * 4;
    const int tr   = (tid >> 4) * 8;
    const int tc   = (tid & 15) * 8;

    float acc[8][8];
#pragma unroll
    for (int i = 0; i < 8; ++i)
#pragma unroll
        for (int j = 0; j < 8; ++j) acc[i][j] = 0.f;

    for (int kt = 0; kt < H2D; kt += 16) {
#pragma unroll
        for (int s = 0; s < 2; ++s) {
            const int m = arow + s * 64;
            const float4 av = *(const float4*)&g_H2[(size_t)(bm + m) * H2D + kt + acol];
            As[(acol + 0) * 132 + m] = av.x;
            As[(acol + 1) * 132 + m] = av.y;
            As[(acol + 2) * 132 + m] = av.z;
            As[(acol + 3) * 132 + m] = av.w;
        }
#pragma unroll
        for (int s = 0; s < 2; ++s) {
            const int k = brow + s * 8;
            *(float4*)&Bs[k * 128 + bcol] =
                *(const float4*)&W3[(size_t)(kt + k) * H3D + bn + bcol];
        }
        __syncthreads();
#pragma unroll
        for (int k = 0; k < 16; ++k) {
            const float4 a0 = *(const float4*)&As[k * 132 + tr];
            const float4 a1 = *(const float4*)&As[k * 132 + tr + 4];
            const float4 b0 = *(const float4*)&Bs[k * 128 + tc];
            const float4 b1v = *(const float4*)&Bs[k * 128 + tc + 4];
            const float am[8] = {a0.x, a0.y, a0.z, a0.w, a1.x, a1.y, a1.z, a1.w};
            const float bnv[8] = {b0.x, b0.y, b0.z, b0.w, b1v.x, b1v.y, b1v.z, b1v.w};
#pragma unroll
            for (int i = 0; i < 8; ++i)
#pragma unroll
                for (int j = 0; j < 8; ++j)
                    acc[i][j] = fmaf(am[i], bnv[j], acc[i][j]);
        }
        __syncthreads();
    }
#pragma unroll
    for (int i = 0; i < 8; ++i) {
        const size_t row = (size_t)(bm + tr + i);
#pragma unroll
        for (int j = 0; j < 8; ++j)
            outh[row * H3D + bn + tc + j] = fmaxf(acc[i][j] + b3[bn + tc + j], 0.f);
    }
}

// ---------------- launch ----------------
extern "C" void kernel_launch(void* const* d_in, const int* in_sizes, int n_in,
                              void* d_out, int out_size)
{
    const float* inf = (const float*)d_in[0];  // input_features (4096, 384)
    const float* Wd  = (const float*)d_in[1];  // W_dec (128, 96)
    const float* bd  = (const float*)d_in[2];  // b_dec (96)
    const float* W1  = (const float*)d_in[3];  // W1 (259, 512)
    const float* b1  = (const float*)d_in[4];  // b1 (512)
    const float* W2  = (const float*)d_in[5];  // W2 (512, 512)
    const float* b2  = (const float*)d_in[6];  // b2 (512)
    const float* W3  = (const float*)d_in[7];  // W3 (512, 256)
    const float* b3  = (const float*)d_in[8];  // b3 (256)
    float* out = (float*)d_out;

    k_dec<<<NPAR, 128>>>(inf, Wd, bd, out + RP_OFF);
    k_cluster<<<NROWS / 256, 256>>>(out + CL_OFF);
    k_f1<<<dim3(NPAR / 128, H1D / 128), 256>>>(inf, W1, b1);
    k_l2<<<dim3(NROWS / 128, H2D / 128), 256>>>(out + RP_OFF, W1, W2, b2);
    k_l3<<<dim3(NROWS / 128, H3D / 128), 256>>>(W3, b3, out + H_OFF);
}

// round 2
// speedup vs baseline: 1.0008x; 1.0008x over previous
#include <cuda_runtime.h>
#include <cuda_bf16.h>
#include <cstddef>

// ---------------- problem constants ----------------
#define NPAR   4096
#define KCH    32
#define NEIGHD 128
#define FEATD  256
#define NROWS  (NPAR * KCH)        // 131072
#define H1D    512
#define H2D    512
#define H3D    256
#define INSTR  (NEIGHD + FEATD)    // 384 input row stride

// output layout: [relative_points (NROWS*3) | h (NROWS*256) | cluster (NROWS)]
#define RP_OFF 0
#define H_OFF  ((size_t)NROWS * 3)                 // 393216
#define CL_OFF (H_OFF + (size_t)NROWS * H3D)       // 33947648

// ---------------- scratch (device globals, no runtime alloc) ----------------
__device__ float g_F1[(size_t)NPAR * H1D];     // features @ W1[:256] + b1   (8 MB)
__device__ float g_H2[(size_t)NROWS * H2D];    // relu(h1 @ W2 + b2)         (256 MB)

// ---------------- kernel 1: decoder GEMM (relative_points) ----------------
// relative_points[p*96 + n] = sum_k neigh[p,k] * W_dec[k,n] + b_dec[n]
__global__ void k_dec(const float* __restrict__ inf, const float* __restrict__ Wd,
                      const float* __restrict__ bd, float* __restrict__ out_rp)
{
    __shared__ float s[NEIGHD];
    const int p = blockIdx.x;
    const int t = threadIdx.x;          // 128 threads
    s[t] = inf[(size_t)p * INSTR + t];
    __syncthreads();
    if (t < 96) {
        float acc = bd[t];
#pragma unroll 8
        for (int k = 0; k < NEIGHD; ++k)
            acc = fmaf(s[k], Wd[k * 96 + t], acc);
        out_rp[(size_t)p * 96 + t] = acc;
    }
}

// ---------------- kernel 2: cluster indices ----------------
__global__ void k_cluster(float* __restrict__ out_cl)
{
    const int i = blockIdx.x * blockDim.x + threadIdx.x;
    if (i < NROWS) out_cl[i] = (float)(i >> 5);
}

// =======================================================================
// Shared 128x128x16 fp32 GEMM skeleton: 256 threads, 8x8 microtile/thread.
// As stored transposed [k][m] with stride 132 (pad kills bank conflicts).
// =======================================================================

// ---------------- kernel 3: F1 = features @ W1[0:256,:] + b1 (no relu) ----
__global__ void k_f1(const float* __restrict__ inf, const float* __restrict__ W1,
                     const float* __restrict__ b1)
{
    __shared__ float As[16 * 132];
    __shared__ float Bs[16 * 128];
    const int tid  = threadIdx.x;
    const int bm   = blockIdx.x * 128;
    const int bn   = blockIdx.y * 128;
    const int arow = tid >> 2;           // 0..63
    const int acol = (tid & 3) * 4;      // 0,4,8,12
    const int brow = tid >> 5;           // 0..7
    const int bcol = (tid & 31) * 4;
    const int tr   = (tid >> 4) * 8;
    const int tc   = (tid & 15) * 8;

    float acc[8][8];
#pragma unroll
    for (int i = 0; i < 8; ++i)
#pragma unroll
        for (int j = 0; j < 8; ++j) acc[i][j] = 0.f;

    for (int kt = 0; kt < FEATD; kt += 16) {
#pragma unroll
        for (int s = 0; s < 2; ++s) {
            const int m = arow + s * 64;
            const float4 av = *(const float4*)&inf[(size_t)(bm + m) * INSTR + NEIGHD + kt + acol];
            As[(acol + 0) * 132 + m] = av.x;
            As[(acol + 1) * 132 + m] = av.y;
            As[(acol + 2) * 132 + m] = av.z;
            As[(acol + 3) * 132 + m] = av.w;
        }
#pragma unroll
        for (int s = 0; s < 2; ++s) {
            const int k = brow + s * 8;
            *(float4*)&Bs[k * 128 + bcol] =
                *(const float4*)&W1[(size_t)(kt + k) * H1D + bn + bcol];
        }
        __syncthreads();
#pragma unroll
        for (int k = 0; k < 16; ++k) {
            const float4 a0 = *(const float4*)&As[k * 132 + tr];
            const float4 a1 = *(const float4*)&As[k * 132 + tr + 4];
            const float4 b0 = *(const float4*)&Bs[k * 128 + tc];
            const float4 b1v = *(const float4*)&Bs[k * 128 + tc + 4];
            const float am[8] = {a0.x, a0.y, a0.z, a0.w, a1.x, a1.y, a1.z, a1.w};
            const float bnv[8] = {b0.x, b0.y, b0.z, b0.w, b1v.x, b1v.y, b1v.z, b1v.w};
#pragma unroll
            for (int i = 0; i < 8; ++i)
#pragma unroll
                for (int j = 0; j < 8; ++j)
                    acc[i][j] = fmaf(am[i], bnv[j], acc[i][j]);
        }
        __syncthreads();
    }
#pragma unroll
    for (int i = 0; i < 8; ++i) {
        const size_t row = (size_t)(bm + tr + i);
#pragma unroll
        for (int j = 0; j < 8; ++j)
            g_F1[row * H1D + bn + tc + j] = acc[i][j] + b1[bn + tc + j];
    }
}

// ---------------- kernel 4: fused h1-rebuild + L2 GEMM ----------------
// h1[r,k] = relu(F1[r>>5,k] + rp[r,0]*W1[256,k] + rp[r,1]*W1[257,k] + rp[r,2]*W1[258,k])
// g_H2 = relu(h1 @ W2 + b2)
__global__ void k_l2(const float* __restrict__ rp, const float* __restrict__ W1,
                     const float* __restrict__ W2, const float* __restrict__ b2)
{
    __shared__ float As[16 * 132];
    __shared__ float Bs[16 * 128];
    __shared__ float w1t[3 * H1D];     // W1 tail rows 256..258, full width
    __shared__ float rps[128 * 3];     // rel points for this row tile
    const int tid  = threadIdx.x;
    const int bm   = blockIdx.x * 128;
    const int bn   = blockIdx.y * 128;
    const int arow = tid >> 2;
    const int acol = (tid & 3) * 4;
    const int brow = tid >> 5;
    const int bcol = (tid & 31) * 4;
    const int tr   = (tid >> 4) * 8;
    const int tc   = (tid & 15) * 8;

    for (int i = tid; i < 3 * H1D; i += 256)
        w1t[i] = W1[(size_t)(FEATD + i / H1D) * H1D + (i % H1D)];
    for (int i = tid; i < 128 * 3; i += 256)
        rps[i] = rp[(size_t)bm * 3 + i];

    float acc[8][8];
#pragma unroll
    for (int i = 0; i < 8; ++i)
#pragma unroll
        for (int j = 0; j < 8; ++j) acc[i][j] = 0.f;

    __syncthreads();   // w1t / rps ready

    for (int kt = 0; kt < H1D; kt += 16) {
#pragma unroll
        for (int s = 0; s < 2; ++s) {
            const int m = arow + s * 64;
            const int parent = (bm + m) >> 5;
            const float r0 = rps[m * 3 + 0];
            const float r1 = rps[m * 3 + 1];
            const float r2 = rps[m * 3 + 2];
            const float4 fv = *(const float4*)&g_F1[(size_t)parent * H1D + kt + acol];
            const float4 wa = *(const float4*)&w1t[kt + acol];
            const float4 wb = *(const float4*)&w1t[H1D + kt + acol];
            const float4 wc = *(const float4*)&w1t[2 * H1D + kt + acol];
            As[(acol + 0) * 132 + m] = fmaxf(fv.x + r0 * wa.x + r1 * wb.x + r2 * wc.x, 0.f);
            As[(acol + 1) * 132 + m] = fmaxf(fv.y + r0 * wa.y + r1 * wb.y + r2 * wc.y, 0.f);
            As[(acol + 2) * 132 + m] = fmaxf(fv.z + r0 * wa.z + r1 * wb.z + r2 * wc.z, 0.f);
            As[(acol + 3) * 132 + m] = fmaxf(fv.w + r0 * wa.w + r1 * wb.w + r2 * wc.w, 0.f);
        }
#pragma unroll
        for (int s = 0; s < 2; ++s) {
            const int k = brow + s * 8;
            *(float4*)&Bs[k * 128 + bcol] =
                *(const float4*)&W2[(size_t)(kt + k) * H2D + bn + bcol];
        }
        __syncthreads();
#pragma unroll
        for (int k = 0; k < 16; ++k) {
            const float4 a0 = *(const float4*)&As[k * 132 + tr];
            const float4 a1 = *(const float4*)&As[k * 132 + tr + 4];
            const float4 b0 = *(const float4*)&Bs[k * 128 + tc];
            const float4 b1v = *(const float4*)&Bs[k * 128 + tc + 4];
            const float am[8] = {a0.x, a0.y, a0.z, a0.w, a1.x, a1.y, a1.z, a1.w};
            const float bnv[8] = {b0.x, b0.y, b0.z, b0.w, b1v.x, b1v.y, b1v.z, b1v.w};
#pragma unroll
            for (int i = 0; i < 8; ++i)
#pragma unroll
                for (int j = 0; j < 8; ++j)
                    acc[i][j] = fmaf(am[i], bnv[j], acc[i][j]);
        }
        __syncthreads();
    }
#pragma unroll
    for (int i = 0; i < 8; ++i) {
        const size_t row = (size_t)(bm + tr + i);
#pragma unroll
        for (int j = 0; j < 8; ++j)
            g_H2[row * H2D + bn + tc + j] = fmaxf(acc[i][j] + b2[bn + tc + j], 0.f);
    }
}

// ---------------- kernel 5: L3 GEMM -> output ----------------
// out_h = relu(g_H2 @ W3 + b3)
__global__ void k_l3(const float* __restrict__ W3, const float* __restrict__ b3,
                     float* __restrict__ outh)
{
    __shared__ float As[16 * 132];
    __shared__ float Bs[16 * 128];
    const int tid  = threadIdx.x;
    const int bm   = blockIdx.x * 128;
    const int bn   = blockIdx.y * 128;
    const int arow = tid >> 2;
    const int acol = (tid & 3) * 4;
    const int brow = tid >> 5;
    const int bcol = (tid & 31) * 4;
    const int tr   = (tid >> 4) * 8;
    const int tc   = (tid & 15) * 8;

    float acc[8][8];
#pragma unroll
    for (int i = 0; i < 8; ++i)
#pragma unroll
        for (int j = 0; j < 8; ++j) acc[i][j] = 0.f;

    for (int kt = 0; kt < H2D; kt += 16) {
#pragma unroll
        for (int s = 0; s < 2; ++s) {
            const int m = arow + s * 64;
            const float4 av = *(const float4*)&g_H2[(size_t)(bm + m) * H2D + kt + acol];
            As[(acol + 0) * 132 + m] = av.x;
            As[(acol + 1) * 132 + m] = av.y;
            As[(acol + 2) * 132 + m] = av.z;
            As[(acol + 3) * 132 + m] = av.w;
        }
#pragma unroll
        for (int s = 0; s < 2; ++s) {
            const int k = brow + s * 8;
            *(float4*)&Bs[k * 128 + bcol] =
                *(const float4*)&W3[(size_t)(kt + k) * H3D + bn + bcol];
        }
        __syncthreads();
#pragma unroll
        for (int k = 0; k < 16; ++k) {
            const float4 a0 = *(const float4*)&As[k * 132 + tr];
            const float4 a1 = *(const float4*)&As[k * 132 + tr + 4];
            const float4 b0 = *(const float4*)&Bs[k * 128 + tc];
            const float4 b1v = *(const float4*)&Bs[k * 128 + tc + 4];
            const float am[8] = {a0.x, a0.y, a0.z, a0.w, a1.x, a1.y, a1.z, a1.w};
            const float bnv[8] = {b0.x, b0.y, b0.z, b0.w, b1v.x, b1v.y, b1v.z, b1v.w};
#pragma unroll
            for (int i = 0; i < 8; ++i)
#pragma unroll
                for (int j = 0; j < 8; ++j)
                    acc[i][j] = fmaf(am[i], bnv[j], acc[i][j]);
        }
        __syncthreads();
    }
#pragma unroll
    for (int i = 0; i < 8; ++i) {
        const size_t row = (size_t)(bm + tr + i);
#pragma unroll
        for (int j = 0; j < 8; ++j)
            outh[row * H3D + bn + tc + j] = fmaxf(acc[i][j] + b3[bn + tc + j], 0.f);
    }
}

// ---------------- launch ----------------
extern "C" void kernel_launch(void* const* d_in, const int* in_sizes, int n_in,
                              void* d_out, int out_size)
{
    const float* inf = (const float*)d_in[0];  // input_features (4096, 384)
    const float* Wd  = (const float*)d_in[1];  // W_dec (128, 96)
    const float* bd  = (const float*)d_in[2];  // b_dec (96)
    const float* W1  = (const float*)d_in[3];  // W1 (259, 512)
    const float* b1  = (const float*)d_in[4];  // b1 (512)
    const float* W2  = (const float*)d_in[5];  // W2 (512, 512)
    const float* b2  = (const float*)d_in[6];  // b2 (512)
    const float* W3  = (const float*)d_in[7];  // W3 (512, 256)
    const float* b3  = (const float*)d_in[8];  // b3 (256)
    float* out = (float*)d_out;

    k_dec<<<NPAR, 128>>>(inf, Wd, bd, out + RP_OFF);
    k_cluster<<<NROWS / 256, 256>>>(out + CL_OFF);
    k_f1<<<dim3(NPAR / 128, H1D / 128), 256>>>(inf, W1, b1);
    k_l2<<<dim3(NROWS / 128, H2D / 128), 256>>>(out + RP_OFF, W1, W2, b2);
    k_l3<<<dim3(NROWS / 128, H3D / 128), 256>>>(W3, b3, out + H_OFF);
}

// round 4
// speedup vs baseline: 2.5456x; 2.5436x over previous
#include <cuda_runtime.h>
#include <cuda_bf16.h>
#include <cstdint>
#include <cstddef>

// ---------------- problem constants ----------------
#define NPAR   4096
#define KCH    32
#define NEIGHD 128
#define FEATD  256
#define NROWS  (NPAR * KCH)        // 131072
#define H1D    512
#define H2D    512
#define H3D    256
#define INSTR  (NEIGHD + FEATD)    // 384

// output layout: [relative_points (NROWS*3) | h (NROWS*256) | cluster (NROWS)]
#define RP_OFF 0
#define H_OFF  ((size_t)NROWS * 3)
#define CL_OFF (H_OFF + (size_t)NROWS * H3D)

// ---------------- scratch (device globals) ----------------
__device__ float    g_F1[(size_t)NPAR * H1D];          // fp32, 8 MB
__device__ uint32_t g_H2s[(size_t)NROWS * H2D];        // packed bf16 hi|lo<<16, 256 MB
__device__ __nv_bfloat16 g_W2Thi[512 * 512], g_W2Tlo[512 * 512];   // W2^T split [n][k]
__device__ __nv_bfloat16 g_W3Thi[256 * 512], g_W3Tlo[256 * 512];   // W3^T split [n][k]

// ---------------- mma helpers (baseline ISA: sm_80+ valid on sm_103) -------
__device__ __forceinline__ uint32_t smem_u32(const void* p) {
    uint32_t a;
    asm("{ .reg .u64 t; cvta.to.shared.u64 t, %1; cvt.u32.u64 %0, t; }" : "=r"(a) : "l"(p));
    return a;
}
__device__ __forceinline__ void ldsm4(uint32_t r[4], uint32_t addr) {
    asm volatile("ldmatrix.sync.aligned.m8n8.x4.shared.b16 {%0,%1,%2,%3}, [%4];"
                 : "=r"(r[0]), "=r"(r[1]), "=r"(r[2]), "=r"(r[3]) : "r"(addr));
}
__device__ __forceinline__ void mma_bf16(float c[4], const uint32_t a[4],
                                         uint32_t b0, uint32_t b1) {
    asm volatile("mma.sync.aligned.m16n8k16.row.col.f32.bf16.bf16.f32 "
                 "{%0,%1,%2,%3}, {%4,%5,%6,%7}, {%8,%9}, {%0,%1,%2,%3};"
                 : "+f"(c[0]), "+f"(c[1]), "+f"(c[2]), "+f"(c[3])
                 : "r"(a[0]), "r"(a[1]), "r"(a[2]), "r"(a[3]), "r"(b0), "r"(b1));
}

// ---------------- SMEM layout: stride 144B rows (16B-aligned, conflict-free)
#define LDA_B     144                 // 72 bf16 per row (kc=64 used)
#define TILE_B    (128 * LDA_B)       // 18432
#define OFF_AHI   0
#define OFF_ALO   TILE_B
#define OFF_BHI   (2 * TILE_B)
#define OFF_BLO   (3 * TILE_B)
#define OFF_W1T   (4 * TILE_B)                 // 3*512 floats = 6144 B
#define OFF_RPS   (OFF_W1T + 6144)             // 128*3 floats = 1536 B
#define SMEM_TOTAL (OFF_RPS + 1536)            // 81408 B

// ---------------- kernel 1: decoder GEMM ----------------
__global__ void k_dec(const float* __restrict__ inf, const float* __restrict__ Wd,
                      const float* __restrict__ bd, float* __restrict__ out_rp)
{
    __shared__ float s[NEIGHD];
    const int p = blockIdx.x;
    const int t = threadIdx.x;
    s[t] = inf[(size_t)p * INSTR + t];
    __syncthreads();
    if (t < 96) {
        float acc = bd[t];
#pragma unroll 8
        for (int k = 0; k < NEIGHD; ++k)
            acc = fmaf(s[k], Wd[k * 96 + t], acc);
        out_rp[(size_t)p * 96 + t] = acc;
    }
}

// ---------------- kernel 2: cluster indices ----------------
__global__ void k_cluster(float* __restrict__ out_cl)
{
    const int i = blockIdx.x * blockDim.x + threadIdx.x;
    if (i < NROWS) out_cl[i] = (float)(i >> 5);
}

// ---------------- kernel 3: F1 = features @ W1[0:256,:] + b1 (fp32 SIMT) ----
__global__ void k_f1(const float* __restrict__ inf, const float* __restrict__ W1,
                     const float* __restrict__ b1)
{
    __shared__ float As[16 * 132];
    __shared__ float Bs[16 * 128];
    const int tid  = threadIdx.x;
    const int bm   = blockIdx.x * 128;
    const int bn   = blockIdx.y * 128;
    const int arow = tid >> 2;
    const int acol = (tid & 3) * 4;
    const int brow = tid >> 5;
    const int bcol = (tid & 31) * 4;
    const int tr   = (tid >> 4) * 8;
    const int tc   = (tid & 15) * 8;

    float acc[8][8];
#pragma unroll
    for (int i = 0; i < 8; ++i)
#pragma unroll
        for (int j = 0; j < 8; ++j) acc[i][j] = 0.f;

    for (int kt = 0; kt < FEATD; kt += 16) {
#pragma unroll
        for (int s = 0; s < 2; ++s) {
            const int m = arow + s * 64;
            const float4 av = *(const float4*)&inf[(size_t)(bm + m) * INSTR + NEIGHD + kt + acol];
            As[(acol + 0) * 132 + m] = av.x;
            As[(acol + 1) * 132 + m] = av.y;
            As[(acol + 2) * 132 + m] = av.z;
            As[(acol + 3) * 132 + m] = av.w;
        }
#pragma unroll
        for (int s = 0; s < 2; ++s) {
            const int k = brow + s * 8;
            *(float4*)&Bs[k * 128 + bcol] =
                *(const float4*)&W1[(size_t)(kt + k) * H1D + bn + bcol];
        }
        __syncthreads();
#pragma unroll
        for (int k = 0; k < 16; ++k) {
            const float4 a0 = *(const float4*)&As[k * 132 + tr];
            const float4 a1 = *(const float4*)&As[k * 132 + tr + 4];
            const float4 b0 = *(const float4*)&Bs[k * 128 + tc];
            const float4 b1v = *(const float4*)&Bs[k * 128 + tc + 4];
            const float am[8] = {a0.x, a0.y, a0.z, a0.w, a1.x, a1.y, a1.z, a1.w};
            const float bnv[8] = {b0.x, b0.y, b0.z, b0.w, b1v.x, b1v.y, b1v.z, b1v.w};
#pragma unroll
            for (int i = 0; i < 8; ++i)
#pragma unroll
                for (int j = 0; j < 8; ++j)
                    acc[i][j] = fmaf(am[i], bnv[j], acc[i][j]);
        }
        __syncthreads();
    }
#pragma unroll
    for (int i = 0; i < 8; ++i) {
        const size_t row = (size_t)(bm + tr + i);
#pragma unroll
        for (int j = 0; j < 8; ++j)
            g_F1[row * H1D + bn + tc + j] = acc[i][j] + b1[bn + tc + j];
    }
}

// ---------------- weight transpose + bf16-split prep ----------------
__global__ void k_prep_w2(const float* __restrict__ W2)
{
    const int idx = blockIdx.x * 256 + threadIdx.x;   // n*512 + k
    const int n = idx >> 9, k = idx & 511;
    const float v = W2[(size_t)k * H2D + n];
    const __nv_bfloat16 h = __float2bfloat16(v);
    g_W2Thi[idx] = h;
    g_W2Tlo[idx] = __float2bfloat16(v - __bfloat162float(h));
}
__global__ void k_prep_w3(const float* __restrict__ W3)
{
    const int idx = blockIdx.x * 256 + threadIdx.x;   // n*512 + k
    const int n = idx >> 9, k = idx & 511;
    const float v = W3[(size_t)k * H3D + n];
    const __nv_bfloat16 h = __float2bfloat16(v);
    g_W3Thi[idx] = h;
    g_W3Tlo[idx] = __float2bfloat16(v - __bfloat162float(h));
}

// =======================================================================
// mma.sync bf16 3-term-split GEMM. CTA tile 128x128, K=512, kc=64.
// 8 warps: warpM = wid&3 (32 rows each), warpN = wid>>2 (64 cols each).
// MODE 0: A = relu(F1[parent] + rp . W1tail), B = W2^T, out = g_H2s packed
// MODE 1: A = unpack(g_H2s),                  B = W3^T, out = fp32 h
// =======================================================================
template<int MODE>
__global__ void __launch_bounds__(256, 2) k_mlp_mma(
    const float* __restrict__ rp, const float* __restrict__ W1,
    const float* __restrict__ bias, float* __restrict__ outf)
{
    extern __shared__ char smem[];
    const uint32_t su = smem_u32(smem);
    const int tid  = threadIdx.x;
    const int wid  = tid >> 5;
    const int lane = tid & 31;
    const int bm   = blockIdx.x * 128;
    const int bn   = blockIdx.y * 128;

    float* w1t = (float*)(smem + OFF_W1T);
    float* rps = (float*)(smem + OFF_RPS);
    if (MODE == 0) {
        for (int i = tid; i < 3 * H1D; i += 256)
            w1t[i] = W1[(size_t)(FEATD + i / H1D) * H1D + (i % H1D)];
        for (int i = tid; i < 128 * 3; i += 256)
            rps[i] = rp[(size_t)bm * 3 + i];
    }

    const int warpM = wid & 3;          // 0..3
    const int warpN = wid >> 2;         // 0..1
    const int rgrp  = tid >> 3;         // 0..31 (prep row group)
    const int c0    = (tid & 7) * 8;    // prep k offset (0..56)

    // ldmatrix lane->address components
    const int a_row  = warpM * 32 + (lane & 15);         // + mblk*16
    const int a_kofs = (lane >> 4) * 8;
    const int b_row  = warpN * 64 + (lane & 7) + ((lane >> 4) << 3);  // + np*16
    const int b_kofs = ((lane >> 3) & 1) * 8;

    float c[2][8][4];
#pragma unroll
    for (int i = 0; i < 2; ++i)
#pragma unroll
        for (int j = 0; j < 8; ++j)
#pragma unroll
            for (int q = 0; q < 4; ++q) c[i][j][q] = 0.f;

    for (int ch = 0; ch < 8; ++ch) {
        const int kt = ch * 64;
        __syncthreads();   // previous compute done before overwriting tiles

        // ---- A tile: 128 x 64 bf16 hi/lo ----
        if (MODE == 0) {
#pragma unroll
            for (int i = 0; i < 4; ++i) {
                const int m = rgrp + 32 * i;
                const int parent = (bm + m) >> 5;
                const float r0 = rps[m * 3 + 0];
                const float r1 = rps[m * 3 + 1];
                const float r2 = rps[m * 3 + 2];
                const float* f = &g_F1[(size_t)parent * H1D + kt + c0];
                float v[8];
#pragma unroll
                for (int j = 0; j < 8; ++j) {
                    const int k = kt + c0 + j;
                    float x = f[j] + r0 * w1t[k] + r1 * w1t[512 + k] + r2 * w1t[1024 + k];
                    v[j] = fmaxf(x, 0.f);
                }
#pragma unroll
                for (int j = 0; j < 4; ++j) {
                    const __nv_bfloat16 h0 = __float2bfloat16(v[2 * j]);
                    const __nv_bfloat16 h1 = __float2bfloat16(v[2 * j + 1]);
                    const float l0 = v[2 * j]     - __bfloat162float(h0);
                    const float l1 = v[2 * j + 1] - __bfloat162float(h1);
                    const uint32_t uh = (uint32_t)__bfloat16_as_ushort(h0) |
                                        ((uint32_t)__bfloat16_as_ushort(h1) << 16);
                    const uint32_t ul = (uint32_t)__bfloat16_as_ushort(__float2bfloat16(l0)) |
                                        ((uint32_t)__bfloat16_as_ushort(__float2bfloat16(l1)) << 16);
                    const int ao = m * LDA_B + (c0 + 2 * j) * 2;
                    *(uint32_t*)(smem + OFF_AHI + ao) = uh;
                    *(uint32_t*)(smem + OFF_ALO + ao) = ul;
                }
            }
        } else {
#pragma unroll
            for (int i = 0; i < 4; ++i) {
                const int m = rgrp + 32 * i;
                const uint32_t* src = &g_H2s[(size_t)(bm + m) * H2D + kt + c0];
                const uint4 p0 = *(const uint4*)src;
                const uint4 p1 = *(const uint4*)(src + 4);
                const uint32_t pk[8] = {p0.x, p0.y, p0.z, p0.w, p1.x, p1.y, p1.z, p1.w};
#pragma unroll
                for (int j = 0; j < 4; ++j) {
                    const uint32_t a = pk[2 * j], b = pk[2 * j + 1];
                    const uint32_t uh = (a & 0xFFFFu) | (b << 16);
                    const uint32_t ul = (a >> 16) | (b & 0xFFFF0000u);
                    const int ao = m * LDA_B + (c0 + 2 * j) * 2;
                    *(uint32_t*)(smem + OFF_AHI + ao) = uh;
                    *(uint32_t*)(smem + OFF_ALO + ao) = ul;
                }
            }
        }

        // ---- B tile: 128 n-rows x 64 k bf16 hi/lo ----
        {
            const __nv_bfloat16* BH = (MODE == 0) ? g_W2Thi : g_W3Thi;
            const __nv_bfloat16* BL = (MODE == 0) ? g_W2Tlo : g_W3Tlo;
#pragma unroll
            for (int i = 0; i < 4; ++i) {
                const int n = rgrp + 32 * i;
                const int bo = n * LDA_B + c0 * 2;     // 16B aligned
                *(uint4*)(smem + OFF_BHI + bo) = *(const uint4*)&BH[(size_t)(bn + n) * 512 + kt + c0];
                *(uint4*)(smem + OFF_BLO + bo) = *(const uint4*)&BL[(size_t)(bn + n) * 512 + kt + c0];
            }
        }
        __syncthreads();

        // ---- compute: 4 x k16 steps ----
#pragma unroll
        for (int ks = 0; ks < 4; ++ks) {
            const int kk = ks * 16;
            uint32_t ah[2][4], al[2][4];
#pragma unroll
            for (int mb = 0; mb < 2; ++mb) {
                const uint32_t aoff = (uint32_t)((a_row + mb * 16) * LDA_B + (kk + a_kofs) * 2);
                ldsm4(ah[mb], su + OFF_AHI + aoff);
                ldsm4(al[mb], su + OFF_ALO + aoff);
            }
#pragma unroll
            for (int np = 0; np < 4; ++np) {
                uint32_t bh[4], bl[4];
                const uint32_t boff = (uint32_t)((b_row + np * 16) * LDA_B + (kk + b_kofs) * 2);
                ldsm4(bh, su + OFF_BHI + boff);
                ldsm4(bl, su + OFF_BLO + boff);
#pragma unroll
                for (int mb = 0; mb < 2; ++mb) {
#pragma unroll
                    for (int ns = 0; ns < 2; ++ns) {
                        float* cc = c[mb][np * 2 + ns];
                        mma_bf16(cc, ah[mb], bh[2 * ns], bh[2 * ns + 1]);
                        mma_bf16(cc, ah[mb], bl[2 * ns], bl[2 * ns + 1]);
                        mma_bf16(cc, al[mb], bh[2 * ns], bh[2 * ns + 1]);
                    }
                }
            }
        }
    }

    // ---- epilogue ----
    const int g   = lane >> 2;
    const int tig = lane & 3;
#pragma unroll
    for (int mb = 0; mb < 2; ++mb) {
#pragma unroll
        for (int nb = 0; nb < 8; ++nb) {
            const int col = bn + warpN * 64 + nb * 8 + tig * 2;
            const float bz0 = bias[col], bz1 = bias[col + 1];
            const int r0 = bm + warpM * 32 + mb * 16 + g;
            const float* cc = c[mb][nb];
#pragma unroll
            for (int half = 0; half < 2; ++half) {
                const int r = r0 + half * 8;
                const float h0 = fmaxf(cc[2 * half + 0] + bz0, 0.f);
                const float h1 = fmaxf(cc[2 * half + 1] + bz1, 0.f);
                if (MODE == 0) {
                    const __nv_bfloat16 hh0 = __float2bfloat16(h0);
                    const __nv_bfloat16 hh1 = __float2bfloat16(h1);
                    const float ll0 = h0 - __bfloat162float(hh0);
                    const float ll1 = h1 - __bfloat162float(hh1);
                    uint2 pk;
                    pk.x = (uint32_t)__bfloat16_as_ushort(hh0) |
                           ((uint32_t)__bfloat16_as_ushort(__float2bfloat16(ll0)) << 16);
                    pk.y = (uint32_t)__bfloat16_as_ushort(hh1) |
                           ((uint32_t)__bfloat16_as_ushort(__float2bfloat16(ll1)) << 16);
                    *(uint2*)&g_H2s[(size_t)r * H2D + col] = pk;
                } else {
                    *(float2*)&outf[(size_t)r * H3D + col] = make_float2(h0, h1);
                }
            }
        }
    }
}

// ---------------- launch ----------------
extern "C" void kernel_launch(void* const* d_in, const int* in_sizes, int n_in,
                              void* d_out, int out_size)
{
    const float* inf = (const float*)d_in[0];
    const float* Wd  = (const float*)d_in[1];
    const float* bd  = (const float*)d_in[2];
    const float* W1  = (const float*)d_in[3];
    const float* b1  = (const float*)d_in[4];
    const float* W2  = (const float*)d_in[5];
    const float* b2  = (const float*)d_in[6];
    const float* W3  = (const float*)d_in[7];
    const float* b3  = (const float*)d_in[8];
    float* out = (float*)d_out;

    cudaFuncSetAttribute(k_mlp_mma<0>, cudaFuncAttributeMaxDynamicSharedMemorySize, SMEM_TOTAL);
    cudaFuncSetAttribute(k_mlp_mma<1>, cudaFuncAttributeMaxDynamicSharedMemorySize, SMEM_TOTAL);

    k_dec<<<NPAR, 128>>>(inf, Wd, bd, out + RP_OFF);
    k_cluster<<<NROWS / 256, 256>>>(out + CL_OFF);
    k_prep_w2<<<512 * 512 / 256, 256>>>(W2);
    k_prep_w3<<<256 * 512 / 256, 256>>>(W3);
    k_f1<<<dim3(NPAR / 128, H1D / 128), 256>>>(inf, W1, b1);
    k_mlp_mma<0><<<dim3(NROWS / 128, H2D / 128), 256, SMEM_TOTAL>>>(out + RP_OFF, W1, b2, nullptr);
    k_mlp_mma<1><<<dim3(NROWS / 128, H3D / 128), 256, SMEM_TOTAL>>>(nullptr, nullptr, b3, out + H_OFF);
}

// round 5
// speedup vs baseline: 2.9624x; 1.1637x over previous
#include <cuda_runtime.h>
#include <cuda_fp16.h>
#include <cstdint>
#include <cstddef>

// ---------------- problem constants ----------------
#define NPAR   4096
#define KCH    32
#define NEIGHD 128
#define FEATD  256
#define NROWS  (NPAR * KCH)        // 131072
#define H1D    512
#define H2D    512
#define H3D    256
#define INSTR  (NEIGHD + FEATD)    // 384

// output layout: [relative_points (NROWS*3) | h (NROWS*256) | cluster (NROWS)]
#define RP_OFF 0
#define H_OFF  ((size_t)NROWS * 3)
#define CL_OFF (H_OFF + (size_t)NROWS * H3D)

// ---------------- scratch (device globals) ----------------
__device__ float    g_F1[(size_t)NPAR * H1D];          // fp32, 8 MB
__device__ uint32_t g_H2s[(size_t)NROWS * H2D];        // packed fp16 hi|lo<<16, 256 MB
__device__ __half   g_W2T[512 * 512];                  // W2^T fp16 [n][k]
__device__ __half   g_W3T[256 * 512];                  // W3^T fp16 [n][k]

// ---------------- mma helpers (baseline ISA: sm_80+ valid on sm_103) -------
__device__ __forceinline__ uint32_t smem_u32(const void* p) {
    uint32_t a;
    asm("{ .reg .u64 t; cvta.to.shared.u64 t, %1; cvt.u32.u64 %0, t; }" : "=r"(a) : "l"(p));
    return a;
}
__device__ __forceinline__ void ldsm4(uint32_t r[4], uint32_t addr) {
    asm volatile("ldmatrix.sync.aligned.m8n8.x4.shared.b16 {%0,%1,%2,%3}, [%4];"
                 : "=r"(r[0]), "=r"(r[1]), "=r"(r[2]), "=r"(r[3]) : "r"(addr));
}
__device__ __forceinline__ void mma_f16(float c[4], const uint32_t a[4],
                                        uint32_t b0, uint32_t b1) {
    asm volatile("mma.sync.aligned.m16n8k16.row.col.f32.f16.f16.f32 "
                 "{%0,%1,%2,%3}, {%4,%5,%6,%7}, {%8,%9}, {%0,%1,%2,%3};"
                 : "+f"(c[0]), "+f"(c[1]), "+f"(c[2]), "+f"(c[3])
                 : "r"(a[0]), "r"(a[1]), "r"(a[2]), "r"(a[3]), "r"(b0), "r"(b1));
}

// ---------------- SMEM layout: stride 144B rows (16B-aligned, conflict-free)
#define LDA_B     144                 // 72 fp16 per row (kc=64 used)
#define TILE_B    (128 * LDA_B)       // 18432
#define OFF_AHI   0
#define OFF_ALO   TILE_B
#define OFF_BHI   (2 * TILE_B)
#define OFF_W1T   (3 * TILE_B)                 // 3*512 floats = 6144 B
#define OFF_RPS   (OFF_W1T + 6144)             // 128*3 floats = 1536 B
#define SMEM_TOTAL (OFF_RPS + 1536)            // 62976 B

// ---------------- kernel 1: decoder GEMM ----------------
__global__ void k_dec(const float* __restrict__ inf, const float* __restrict__ Wd,
                      const float* __restrict__ bd, float* __restrict__ out_rp)
{
    __shared__ float s[NEIGHD];
    const int p = blockIdx.x;
    const int t = threadIdx.x;
    s[t] = inf[(size_t)p * INSTR + t];
    __syncthreads();
    if (t < 96) {
        float acc = bd[t];
#pragma unroll 8
        for (int k = 0; k < NEIGHD; ++k)
            acc = fmaf(s[k], Wd[k * 96 + t], acc);
        out_rp[(size_t)p * 96 + t] = acc;
    }
}

// ---------------- kernel 2: cluster indices ----------------
__global__ void k_cluster(float* __restrict__ out_cl)
{
    const int i = blockIdx.x * blockDim.x + threadIdx.x;
    if (i < NROWS) out_cl[i] = (float)(i >> 5);
}

// ---------------- kernel 3: F1 = features @ W1[0:256,:] + b1 (fp32 SIMT) ----
__global__ void k_f1(const float* __restrict__ inf, const float* __restrict__ W1,
                     const float* __restrict__ b1)
{
    __shared__ float As[16 * 132];
    __shared__ float Bs[16 * 128];
    const int tid  = threadIdx.x;
    const int bm   = blockIdx.x * 128;
    const int bn   = blockIdx.y * 128;
    const int arow = tid >> 2;
    const int acol = (tid & 3) * 4;
    const int brow = tid >> 5;
    const int bcol = (tid & 31) * 4;
    const int tr   = (tid >> 4) * 8;
    const int tc   = (tid & 15) * 8;

    float acc[8][8];
#pragma unroll
    for (int i = 0; i < 8; ++i)
#pragma unroll
        for (int j = 0; j < 8; ++j) acc[i][j] = 0.f;

    for (int kt = 0; kt < FEATD; kt += 16) {
#pragma unroll
        for (int s = 0; s < 2; ++s) {
            const int m = arow + s * 64;
            const float4 av = *(const float4*)&inf[(size_t)(bm + m) * INSTR + NEIGHD + kt + acol];
            As[(acol + 0) * 132 + m] = av.x;
            As[(acol + 1) * 132 + m] = av.y;
            As[(acol + 2) * 132 + m] = av.z;
            As[(acol + 3) * 132 + m] = av.w;
        }
#pragma unroll
        for (int s = 0; s < 2; ++s) {
            const int k = brow + s * 8;
            *(float4*)&Bs[k * 128 + bcol] =
                *(const float4*)&W1[(size_t)(kt + k) * H1D + bn + bcol];
        }
        __syncthreads();
#pragma unroll
        for (int k = 0; k < 16; ++k) {
            const float4 a0 = *(const float4*)&As[k * 132 + tr];
            const float4 a1 = *(const float4*)&As[k * 132 + tr + 4];
            const float4 b0 = *(const float4*)&Bs[k * 128 + tc];
            const float4 b1v = *(const float4*)&Bs[k * 128 + tc + 4];
            const float am[8] = {a0.x, a0.y, a0.z, a0.w, a1.x, a1.y, a1.z, a1.w};
            const float bnv[8] = {b0.x, b0.y, b0.z, b0.w, b1v.x, b1v.y, b1v.z, b1v.w};
#pragma unroll
            for (int i = 0; i < 8; ++i)
#pragma unroll
                for (int j = 0; j < 8; ++j)
                    acc[i][j] = fmaf(am[i], bnv[j], acc[i][j]);
        }
        __syncthreads();
    }
#pragma unroll
    for (int i = 0; i < 8; ++i) {
        const size_t row = (size_t)(bm + tr + i);
#pragma unroll
        for (int j = 0; j < 8; ++j)
            g_F1[row * H1D + bn + tc + j] = acc[i][j] + b1[bn + tc + j];
    }
}

// ---------------- weight transpose + fp16 prep ----------------
__global__ void k_prep_w2(const float* __restrict__ W2)
{
    const int idx = blockIdx.x * 256 + threadIdx.x;   // n*512 + k
    const int n = idx >> 9, k = idx & 511;
    g_W2T[idx] = __float2half(W2[(size_t)k * H2D + n]);
}
__global__ void k_prep_w3(const float* __restrict__ W3)
{
    const int idx = blockIdx.x * 256 + threadIdx.x;   // n*512 + k
    const int n = idx >> 9, k = idx & 511;
    g_W3T[idx] = __float2half(W3[(size_t)k * H3D + n]);
}

// =======================================================================
// mma.sync fp16 A-split GEMM. CTA tile 128x128, K=512, kc=64.
// A = Ahi + Alo (fp16 pair, ~22 mantissa bits); B single fp16.
// D = Ahi*B + Alo*B  -> 2 MMAs per k16 step.
// 8 warps: warpM = wid&3 (32 rows each), warpN = wid>>2 (64 cols each).
// MODE 0: A = relu(F1[parent] + rp . W1tail), B = W2^T, out = g_H2s packed
// MODE 1: A = unpack(g_H2s),                  B = W3^T, out = fp32 h
// =======================================================================
template<int MODE>
__global__ void __launch_bounds__(256, 2) k_mlp_mma(
    const float* __restrict__ rp, const float* __restrict__ W1,
    const float* __restrict__ bias, float* __restrict__ outf)
{
    extern __shared__ char smem[];
    const uint32_t su = smem_u32(smem);
    const int tid  = threadIdx.x;
    const int wid  = tid >> 5;
    const int lane = tid & 31;
    const int bm   = blockIdx.x * 128;
    const int bn   = blockIdx.y * 128;

    float* w1t = (float*)(smem + OFF_W1T);
    float* rps = (float*)(smem + OFF_RPS);
    if (MODE == 0) {
        for (int i = tid; i < 3 * H1D; i += 256)
            w1t[i] = W1[(size_t)(FEATD + i / H1D) * H1D + (i % H1D)];
        for (int i = tid; i < 128 * 3; i += 256)
            rps[i] = rp[(size_t)bm * 3 + i];
    }

    const int warpM = wid & 3;          // 0..3
    const int warpN = wid >> 2;         // 0..1
    const int rgrp  = tid >> 3;         // 0..31 (prep row group)
    const int c0    = (tid & 7) * 8;    // prep k offset (0..56)

    // ldmatrix lane->address components
    const int a_row  = warpM * 32 + (lane & 15);         // + mblk*16
    const int a_kofs = (lane >> 4) * 8;
    const int b_row  = warpN * 64 + (lane & 7) + ((lane >> 4) << 3);  // + np*16
    const int b_kofs = ((lane >> 3) & 1) * 8;

    float c[2][8][4];
#pragma unroll
    for (int i = 0; i < 2; ++i)
#pragma unroll
        for (int j = 0; j < 8; ++j)
#pragma unroll
            for (int q = 0; q < 4; ++q) c[i][j][q] = 0.f;

    for (int ch = 0; ch < 8; ++ch) {
        const int kt = ch * 64;
        __syncthreads();   // previous compute done before overwriting tiles

        // ---- A tile: 128 x 64 fp16 hi/lo ----
        if (MODE == 0) {
#pragma unroll
            for (int i = 0; i < 4; ++i) {
                const int m = rgrp + 32 * i;
                const int parent = (bm + m) >> 5;
                const float r0 = rps[m * 3 + 0];
                const float r1 = rps[m * 3 + 1];
                const float r2 = rps[m * 3 + 2];
                const float* f = &g_F1[(size_t)parent * H1D + kt + c0];
                float v[8];
#pragma unroll
                for (int j = 0; j < 8; ++j) {
                    const int k = kt + c0 + j;
                    float x = f[j] + r0 * w1t[k] + r1 * w1t[512 + k] + r2 * w1t[1024 + k];
                    v[j] = fmaxf(x, 0.f);
                }
#pragma unroll
                for (int j = 0; j < 4; ++j) {
                    const __half h0 = __float2half(v[2 * j]);
                    const __half h1 = __float2half(v[2 * j + 1]);
                    const float l0 = v[2 * j]     - __half2float(h0);
                    const float l1 = v[2 * j + 1] - __half2float(h1);
                    const uint32_t uh = (uint32_t)__half_as_ushort(h0) |
                                        ((uint32_t)__half_as_ushort(h1) << 16);
                    const uint32_t ul = (uint32_t)__half_as_ushort(__float2half(l0)) |
                                        ((uint32_t)__half_as_ushort(__float2half(l1)) << 16);
                    const int ao = m * LDA_B + (c0 + 2 * j) * 2;
                    *(uint32_t*)(smem + OFF_AHI + ao) = uh;
                    *(uint32_t*)(smem + OFF_ALO + ao) = ul;
                }
            }
        } else {
#pragma unroll
            for (int i = 0; i < 4; ++i) {
                const int m = rgrp + 32 * i;
                const uint32_t* src = &g_H2s[(size_t)(bm + m) * H2D + kt + c0];
                const uint4 p0 = *(const uint4*)src;
                const uint4 p1 = *(const uint4*)(src + 4);
                const uint32_t pk[8] = {p0.x, p0.y, p0.z, p0.w, p1.x, p1.y, p1.z, p1.w};
#pragma unroll
                for (int j = 0; j < 4; ++j) {
                    const uint32_t a = pk[2 * j], b = pk[2 * j + 1];
                    const uint32_t uh = (a & 0xFFFFu) | (b << 16);
                    const uint32_t ul = (a >> 16) | (b & 0xFFFF0000u);
                    const int ao = m * LDA_B + (c0 + 2 * j) * 2;
                    *(uint32_t*)(smem + OFF_AHI + ao) = uh;
                    *(uint32_t*)(smem + OFF_ALO + ao) = ul;
                }
            }
        }

        // ---- B tile: 128 n-rows x 64 k fp16 ----
        {
            const __half* BH = (MODE == 0) ? g_W2T : g_W3T;
#pragma unroll
            for (int i = 0; i < 4; ++i) {
                const int n = rgrp + 32 * i;
                const int bo = n * LDA_B + c0 * 2;     // 16B aligned
                *(uint4*)(smem + OFF_BHI + bo) = *(const uint4*)&BH[(size_t)(bn + n) * 512 + kt + c0];
            }
        }
        __syncthreads();

        // ---- compute: 4 x k16 steps, 2 MMAs per (mb, ns) ----
#pragma unroll
        for (int ks = 0; ks < 4; ++ks) {
            const int kk = ks * 16;
            uint32_t ah[2][4], al[2][4];
#pragma unroll
            for (int mb = 0; mb < 2; ++mb) {
                const uint32_t aoff = (uint32_t)((a_row + mb * 16) * LDA_B + (kk + a_kofs) * 2);
                ldsm4(ah[mb], su + OFF_AHI + aoff);
                ldsm4(al[mb], su + OFF_ALO + aoff);
            }
#pragma unroll
            for (int np = 0; np < 4; ++np) {
                uint32_t bh[4];
                const uint32_t boff = (uint32_t)((b_row + np * 16) * LDA_B + (kk + b_kofs) * 2);
                ldsm4(bh, su + OFF_BHI + boff);
#pragma unroll
                for (int mb = 0; mb < 2; ++mb) {
#pragma unroll
                    for (int ns = 0; ns < 2; ++ns) {
                        float* cc = c[mb][np * 2 + ns];
                        mma_f16(cc, ah[mb], bh[2 * ns], bh[2 * ns + 1]);
                        mma_f16(cc, al[mb], bh[2 * ns], bh[2 * ns + 1]);
                    }
                }
            }
        }
    }

    // ---- epilogue ----
    const int g   = lane >> 2;
    const int tig = lane & 3;
#pragma unroll
    for (int mb = 0; mb < 2; ++mb) {
#pragma unroll
        for (int nb = 0; nb < 8; ++nb) {
            const int col = bn + warpN * 64 + nb * 8 + tig * 2;
            const float bz0 = bias[col], bz1 = bias[col + 1];
            const int r0 = bm + warpM * 32 + mb * 16 + g;
            const float* cc = c[mb][nb];
#pragma unroll
            for (int half = 0; half < 2; ++half) {
                const int r = r0 + half * 8;
                const float h0 = fmaxf(cc[2 * half + 0] + bz0, 0.f);
                const float h1 = fmaxf(cc[2 * half + 1] + bz1, 0.f);
                if (MODE == 0) {
                    const __half hh0 = __float2half(h0);
                    const __half hh1 = __float2half(h1);
                    const float ll0 = h0 - __half2float(hh0);
                    const float ll1 = h1 - __half2float(hh1);
                    uint2 pk;
                    pk.x = (uint32_t)__half_as_ushort(hh0) |
                           ((uint32_t)__half_as_ushort(__float2half(ll0)) << 16);
                    pk.y = (uint32_t)__half_as_ushort(hh1) |
                           ((uint32_t)__half_as_ushort(__float2half(ll1)) << 16);
                    *(uint2*)&g_H2s[(size_t)r * H2D + col] = pk;
                } else {
                    *(float2*)&outf[(size_t)r * H3D + col] = make_float2(h0, h1);
                }
            }
        }
    }
}

// ---------------- launch ----------------
extern "C" void kernel_launch(void* const* d_in, const int* in_sizes, int n_in,
                              void* d_out, int out_size)
{
    const float* inf = (const float*)d_in[0];
    const float* Wd  = (const float*)d_in[1];
    const float* bd  = (const float*)d_in[2];
    const float* W1  = (const float*)d_in[3];
    const float* b1  = (const float*)d_in[4];
    const float* W2  = (const float*)d_in[5];
    const float* b2  = (const float*)d_in[6];
    const float* W3  = (const float*)d_in[7];
    const float* b3  = (const float*)d_in[8];
    float* out = (float*)d_out;

    cudaFuncSetAttribute(k_mlp_mma<0>, cudaFuncAttributeMaxDynamicSharedMemorySize, SMEM_TOTAL);
    cudaFuncSetAttribute(k_mlp_mma<1>, cudaFuncAttributeMaxDynamicSharedMemorySize, SMEM_TOTAL);

    k_dec<<<NPAR, 128>>>(inf, Wd, bd, out + RP_OFF);
    k_cluster<<<NROWS / 256, 256>>>(out + CL_OFF);
    k_prep_w2<<<512 * 512 / 256, 256>>>(W2);
    k_prep_w3<<<256 * 512 / 256, 256>>>(W3);
    k_f1<<<dim3(NPAR / 128, H1D / 128), 256>>>(inf, W1, b1);
    k_mlp_mma<0><<<dim3(NROWS / 128, H2D / 128), 256, SMEM_TOTAL>>>(out + RP_OFF, W1, b2, nullptr);
    k_mlp_mma<1><<<dim3(NROWS / 128, H3D / 128), 256, SMEM_TOTAL>>>(nullptr, nullptr, b3, out + H_OFF);
}

// round 6
// speedup vs baseline: 3.5450x; 1.1967x over previous
#include <cuda_runtime.h>
#include <cuda_fp16.h>
#include <cstdint>
#include <cstddef>

// ---------------- problem constants ----------------
#define NPAR   4096
#define KCH    32
#define NEIGHD 128
#define FEATD  256
#define NROWS  (NPAR * KCH)        // 131072
#define H1D    512
#define H2D    512
#define H3D    256
#define INSTR  (NEIGHD + FEATD)    // 384

// output layout: [relative_points (NROWS*3) | h (NROWS*256) | cluster (NROWS)]
#define RP_OFF 0
#define H_OFF  ((size_t)NROWS * 3)
#define CL_OFF (H_OFF + (size_t)NROWS * H3D)

// ---------------- scratch (device globals) ----------------
__device__ float  g_F1[(size_t)NPAR * H1D];      // fp32, 8 MB
__device__ __half g_H2h[(size_t)NROWS * H2D];    // h2 plain fp16, 128 MB
__device__ __half g_W2T[512 * 512];              // W2^T fp16 [n][k]
__device__ __half g_W3T[256 * 512];              // W3^T fp16 [n][k]

// ---------------- mma helpers ----------------
__device__ __forceinline__ uint32_t smem_u32(const void* p) {
    uint32_t a;
    asm("{ .reg .u64 t; cvta.to.shared.u64 t, %1; cvt.u32.u64 %0, t; }" : "=r"(a) : "l"(p));
    return a;
}
__device__ __forceinline__ void ldsm4(uint32_t r[4], uint32_t addr) {
    asm volatile("ldmatrix.sync.aligned.m8n8.x4.shared.b16 {%0,%1,%2,%3}, [%4];"
                 : "=r"(r[0]), "=r"(r[1]), "=r"(r[2]), "=r"(r[3]) : "r"(addr));
}
__device__ __forceinline__ void mma_f16(float c[4], const uint32_t a[4],
                                        uint32_t b0, uint32_t b1) {
    asm volatile("mma.sync.aligned.m16n8k16.row.col.f32.f16.f16.f32 "
                 "{%0,%1,%2,%3}, {%4,%5,%6,%7}, {%8,%9}, {%0,%1,%2,%3};"
                 : "+f"(c[0]), "+f"(c[1]), "+f"(c[2]), "+f"(c[3])
                 : "r"(a[0]), "r"(a[1]), "r"(a[2]), "r"(a[3]), "r"(b0), "r"(b1));
}

// ---------------- SMEM layout ----------------
// kc=32 chunks; tile row = 32 halves = 64B, padded to 80B (16B aligned,
// 8 rows at stride 80 hit 8 distinct 16B bank groups -> conflict-free ldsm).
#define KC      32
#define NCH0    (H1D / KC)            // 16 chunks (K=512)
#define LDT     80
#define TILE_B  (128 * LDT)           // 10240
#define OFF_AHI 0
#define OFF_ALO TILE_B
#define OFF_B   (2 * TILE_B)
#define BUFSZ   (3 * TILE_B)          // 30720
#define OFF_W1T (2 * BUFSZ)           // 61440, 3*512 floats = 6144
#define OFF_RPS (OFF_W1T + 6144)      // 128*3 floats = 1536
#define SMEM_TOTAL (OFF_RPS + 1536)   // 69120

// ---------------- kernel 1: decoder GEMM ----------------
__global__ void k_dec(const float* __restrict__ inf, const float* __restrict__ Wd,
                      const float* __restrict__ bd, float* __restrict__ out_rp)
{
    __shared__ float s[NEIGHD];
    const int p = blockIdx.x;
    const int t = threadIdx.x;
    s[t] = inf[(size_t)p * INSTR + t];
    __syncthreads();
    if (t < 96) {
        float acc = bd[t];
#pragma unroll 8
        for (int k = 0; k < NEIGHD; ++k)
            acc = fmaf(s[k], Wd[k * 96 + t], acc);
        out_rp[(size_t)p * 96 + t] = acc;
    }
}

// ---------------- kernel 2: cluster indices ----------------
__global__ void k_cluster(float* __restrict__ out_cl)
{
    const int i = blockIdx.x * blockDim.x + threadIdx.x;
    if (i < NROWS) out_cl[i] = (float)(i >> 5);
}

// ---------------- kernel 3: F1 = features @ W1[0:256,:] + b1 (fp32 SIMT) ----
__global__ void k_f1(const float* __restrict__ inf, const float* __restrict__ W1,
                     const float* __restrict__ b1)
{
    __shared__ float As[16 * 132];
    __shared__ float Bs[16 * 128];
    const int tid  = threadIdx.x;
    const int bm   = blockIdx.x * 128;
    const int bn   = blockIdx.y * 128;
    const int arow = tid >> 2;
    const int acol = (tid & 3) * 4;
    const int brow = tid >> 5;
    const int bcol = (tid & 31) * 4;
    const int tr   = (tid >> 4) * 8;
    const int tc   = (tid & 15) * 8;

    float acc[8][8];
#pragma unroll
    for (int i = 0; i < 8; ++i)
#pragma unroll
        for (int j = 0; j < 8; ++j) acc[i][j] = 0.f;

    for (int kt = 0; kt < FEATD; kt += 16) {
#pragma unroll
        for (int s = 0; s < 2; ++s) {
            const int m = arow + s * 64;
            const float4 av = *(const float4*)&inf[(size_t)(bm + m) * INSTR + NEIGHD + kt + acol];
            As[(acol + 0) * 132 + m] = av.x;
            As[(acol + 1) * 132 + m] = av.y;
            As[(acol + 2) * 132 + m] = av.z;
            As[(acol + 3) * 132 + m] = av.w;
        }
#pragma unroll
        for (int s = 0; s < 2; ++s) {
            const int k = brow + s * 8;
            *(float4*)&Bs[k * 128 + bcol] =
                *(const float4*)&W1[(size_t)(kt + k) * H1D + bn + bcol];
        }
        __syncthreads();
#pragma unroll
        for (int k = 0; k < 16; ++k) {
            const float4 a0 = *(const float4*)&As[k * 132 + tr];
            const float4 a1 = *(const float4*)&As[k * 132 + tr + 4];
            const float4 b0 = *(const float4*)&Bs[k * 128 + tc];
            const float4 b1v = *(const float4*)&Bs[k * 128 + tc + 4];
            const float am[8] = {a0.x, a0.y, a0.z, a0.w, a1.x, a1.y, a1.z, a1.w};
            const float bnv[8] = {b0.x, b0.y, b0.z, b0.w, b1v.x, b1v.y, b1v.z, b1v.w};
#pragma unroll
            for (int i = 0; i < 8; ++i)
#pragma unroll
                for (int j = 0; j < 8; ++j)
                    acc[i][j] = fmaf(am[i], bnv[j], acc[i][j]);
        }
        __syncthreads();
    }
#pragma unroll
    for (int i = 0; i < 8; ++i) {
        const size_t row = (size_t)(bm + tr + i);
#pragma unroll
        for (int j = 0; j < 8; ++j)
            g_F1[row * H1D + bn + tc + j] = acc[i][j] + b1[bn + tc + j];
    }
}

// ---------------- weight transpose + fp16 prep ----------------
__global__ void k_prep_w2(const float* __restrict__ W2)
{
    const int idx = blockIdx.x * 256 + threadIdx.x;   // n*512 + k
    const int n = idx >> 9, k = idx & 511;
    g_W2T[idx] = __float2half(W2[(size_t)k * H2D + n]);
}
__global__ void k_prep_w3(const float* __restrict__ W3)
{
    const int idx = blockIdx.x * 256 + threadIdx.x;   // n*512 + k
    const int n = idx >> 9, k = idx & 511;
    g_W3T[idx] = __float2half(W3[(size_t)k * H3D + n]);
}

// =======================================================================
// Double-buffered mma.sync fp16 GEMM. CTA tile 128x128, K=512, kc=32.
// MODE 0: A = relu(F1[parent] + rp.W1tail), split fp16 hi+lo (2 MMA terms),
//         B = W2^T fp16, out = g_H2h plain fp16.
// MODE 1: A = g_H2h fp16 (1 MMA term), B = W3^T fp16, out = fp32 h.
// Pipeline: prefetch globals (c+1) -> MMA(c) -> cvt+STS(c+1) -> barrier.
// =======================================================================
template<int MODE>
__global__ void __launch_bounds__(256, 2) k_mlp_mma(
    const float* __restrict__ rp, const float* __restrict__ W1,
    const float* __restrict__ bias, float* __restrict__ outf)
{
    extern __shared__ char smem[];
    const uint32_t su = smem_u32(smem);
    const int tid  = threadIdx.x;
    const int wid  = tid >> 5;
    const int lane = tid & 31;
    const int bm   = blockIdx.x * 128;
    const int bn   = blockIdx.y * 128;

    float* w1t = (float*)(smem + OFF_W1T);
    float* rps = (float*)(smem + OFF_RPS);
    if (MODE == 0) {
        for (int i = tid; i < 3 * H1D; i += 256)
            w1t[i] = W1[(size_t)(FEATD + i / H1D) * H1D + (i % H1D)];
        for (int i = tid; i < 128 * 3; i += 256)
            rps[i] = rp[(size_t)bm * 3 + i];
    }
    __syncthreads();

    const int warpM = wid & 3;
    const int warpN = wid >> 2;
    const int prow  = tid >> 1;            // 0..127 (prep row)
    const int pc0   = (tid & 1) * 16;      // 0 or 16 (prep k offset)

    const int a_row  = warpM * 32 + (lane & 15);
    const int a_kofs = (lane >> 4) * 8;
    const int b_row  = warpN * 64 + (lane & 7) + ((lane >> 4) << 3);
    const int b_kofs = ((lane >> 3) & 1) * 8;

    const __half* Bsrc = (MODE == 0) ? g_W2T : g_W3T;

    float c[2][8][4];
#pragma unroll
    for (int i = 0; i < 2; ++i)
#pragma unroll
        for (int j = 0; j < 8; ++j)
#pragma unroll
            for (int q = 0; q < 4; ++q) c[i][j][q] = 0.f;

    // prefetch registers
    float4 pf[4];      // MODE0: F1 segment (16 floats)
    uint4  pa[2];      // MODE1: A fp16 (16 halves)
    uint4  pb[2];      // B fp16 (16 halves)

    auto fetch = [&](int ch) {
        const int kt = ch * KC;
        if (MODE == 0) {
            const float* f = &g_F1[(size_t)((bm + prow) >> 5) * H1D + kt + pc0];
#pragma unroll
            for (int q = 0; q < 4; ++q) pf[q] = *(const float4*)(f + 4 * q);
        } else {
            const __half* a = &g_H2h[(size_t)(bm + prow) * H2D + kt + pc0];
            pa[0] = *(const uint4*)a;
            pa[1] = *(const uint4*)(a + 8);
        }
        const __half* b = &Bsrc[(size_t)(bn + prow) * 512 + kt + pc0];
        pb[0] = *(const uint4*)b;
        pb[1] = *(const uint4*)(b + 8);
    };

    auto stage = [&](int ch, int buf) {
        char* base = smem + buf * BUFSZ;
        const int kt = ch * KC;
        if (MODE == 0) {
            const float r0 = rps[prow * 3 + 0];
            const float r1 = rps[prow * 3 + 1];
            const float r2 = rps[prow * 3 + 2];
            const float* fv = (const float*)pf;
            uint32_t uh[8], ul[8];
#pragma unroll
            for (int j = 0; j < 8; ++j) {
                const int k0 = kt + pc0 + 2 * j;
                float v0 = fmaxf(fv[2*j]   + r0 * w1t[k0]   + r1 * w1t[512 + k0]   + r2 * w1t[1024 + k0],   0.f);
                float v1 = fmaxf(fv[2*j+1] + r0 * w1t[k0+1] + r1 * w1t[512 + k0+1] + r2 * w1t[1024 + k0+1], 0.f);
                const __half h0 = __float2half(v0);
                const __half h1 = __float2half(v1);
                const float l0 = v0 - __half2float(h0);
                const float l1 = v1 - __half2float(h1);
                uh[j] = (uint32_t)__half_as_ushort(h0) | ((uint32_t)__half_as_ushort(h1) << 16);
                ul[j] = (uint32_t)__half_as_ushort(__float2half(l0)) |
                        ((uint32_t)__half_as_ushort(__float2half(l1)) << 16);
            }
            const int ao = prow * LDT + pc0 * 2;
            *(uint4*)(base + OFF_AHI + ao)      = make_uint4(uh[0], uh[1], uh[2], uh[3]);
            *(uint4*)(base + OFF_AHI + ao + 16) = make_uint4(uh[4], uh[5], uh[6], uh[7]);
            *(uint4*)(base + OFF_ALO + ao)      = make_uint4(ul[0], ul[1], ul[2], ul[3]);
            *(uint4*)(base + OFF_ALO + ao + 16) = make_uint4(ul[4], ul[5], ul[6], ul[7]);
        } else {
            const int ao = prow * LDT + pc0 * 2;
            *(uint4*)(base + OFF_AHI + ao)      = pa[0];
            *(uint4*)(base + OFF_AHI + ao + 16) = pa[1];
        }
        const int bo = prow * LDT + pc0 * 2;
        *(uint4*)(base + OFF_B + bo)      = pb[0];
        *(uint4*)(base + OFF_B + bo + 16) = pb[1];
    };

    auto domma = [&](int buf) {
        const uint32_t base = su + buf * BUFSZ;
#pragma unroll
        for (int ks = 0; ks < 2; ++ks) {
            const int kk = ks * 16;
            uint32_t ah[2][4], al[2][4];
#pragma unroll
            for (int mb = 0; mb < 2; ++mb) {
                const uint32_t aoff = (uint32_t)((a_row + mb * 16) * LDT + (kk + a_kofs) * 2);
                ldsm4(ah[mb], base + OFF_AHI + aoff);
                if (MODE == 0) ldsm4(al[mb], base + OFF_ALO + aoff);
            }
#pragma unroll
            for (int np = 0; np < 4; ++np) {
                uint32_t bh[4];
                const uint32_t boff = (uint32_t)((b_row + np * 16) * LDT + (kk + b_kofs) * 2);
                ldsm4(bh, base + OFF_B + boff);
#pragma unroll
                for (int mb = 0; mb < 2; ++mb) {
#pragma unroll
                    for (int ns = 0; ns < 2; ++ns) {
                        float* cc = c[mb][np * 2 + ns];
                        mma_f16(cc, ah[mb], bh[2 * ns], bh[2 * ns + 1]);
                        if (MODE == 0) mma_f16(cc, al[mb], bh[2 * ns], bh[2 * ns + 1]);
                    }
                }
            }
        }
    };

    // -------- pipeline --------
    fetch(0);
    stage(0, 0);
    __syncthreads();
#pragma unroll 1
    for (int ch = 0; ch < NCH0; ++ch) {
        if (ch + 1 < NCH0) fetch(ch + 1);
        domma(ch & 1);
        if (ch + 1 < NCH0) stage(ch + 1, (ch + 1) & 1);
        __syncthreads();
    }

    // -------- epilogue --------
    const int g   = lane >> 2;
    const int tig = lane & 3;
#pragma unroll
    for (int mb = 0; mb < 2; ++mb) {
#pragma unroll
        for (int nb = 0; nb < 8; ++nb) {
            const int col = bn + warpN * 64 + nb * 8 + tig * 2;
            const float bz0 = bias[col], bz1 = bias[col + 1];
            const int r0 = bm + warpM * 32 + mb * 16 + g;
            const float* cc = c[mb][nb];
#pragma unroll
            for (int half = 0; half < 2; ++half) {
                const int r = r0 + half * 8;
                const float h0 = fmaxf(cc[2 * half + 0] + bz0, 0.f);
                const float h1 = fmaxf(cc[2 * half + 1] + bz1, 0.f);
                if (MODE == 0) {
                    __half2 hv = __halves2half2(__float2half(h0), __float2half(h1));
                    *(__half2*)&g_H2h[(size_t)r * H2D + col] = hv;
                } else {
                    *(float2*)&outf[(size_t)r * H3D + col] = make_float2(h0, h1);
                }
            }
        }
    }
}

// ---------------- launch ----------------
extern "C" void kernel_launch(void* const* d_in, const int* in_sizes, int n_in,
                              void* d_out, int out_size)
{
    const float* inf = (const float*)d_in[0];
    const float* Wd  = (const float*)d_in[1];
    const float* bd  = (const float*)d_in[2];
    const float* W1  = (const float*)d_in[3];
    const float* b1  = (const float*)d_in[4];
    const float* W2  = (const float*)d_in[5];
    const float* b2  = (const float*)d_in[6];
    const float* W3  = (const float*)d_in[7];
    const float* b3  = (const float*)d_in[8];
    float* out = (float*)d_out;

    cudaFuncSetAttribute(k_mlp_mma<0>, cudaFuncAttributeMaxDynamicSharedMemorySize, SMEM_TOTAL);
    cudaFuncSetAttribute(k_mlp_mma<1>, cudaFuncAttributeMaxDynamicSharedMemorySize, SMEM_TOTAL);

    k_dec<<<NPAR, 128>>>(inf, Wd, bd, out + RP_OFF);
    k_cluster<<<NROWS / 256, 256>>>(out + CL_OFF);
    k_prep_w2<<<512 * 512 / 256, 256>>>(W2);
    k_prep_w3<<<256 * 512 / 256, 256>>>(W3);
    k_f1<<<dim3(NPAR / 128, H1D / 128), 256>>>(inf, W1, b1);
    k_mlp_mma<0><<<dim3(NROWS / 128, H2D / 128), 256, SMEM_TOTAL>>>(out + RP_OFF, W1, b2, nullptr);
    k_mlp_mma<1><<<dim3(NROWS / 128, H3D / 128), 256, SMEM_TOTAL>>>(nullptr, nullptr, b3, out + H_OFF);
}

// round 7
// speedup vs baseline: 4.1422x; 1.1685x over previous
#include <cuda_runtime.h>
#include <cuda_fp16.h>
#include <cstdint>
#include <cstddef>

// ---------------- problem constants ----------------
#define NPAR   4096
#define KCH    32
#define NEIGHD 128
#define FEATD  256
#define NROWS  (NPAR * KCH)        // 131072
#define H1D    512
#define H2D    512
#define H3D    256
#define INSTR  (NEIGHD + FEATD)    // 384

// output layout: [relative_points (NROWS*3) | h (NROWS*256) | cluster (NROWS)]
#define RP_OFF 0
#define H_OFF  ((size_t)NROWS * 3)
#define CL_OFF (H_OFF + (size_t)NROWS * H3D)

// ---------------- scratch (device globals) ----------------
__device__ float  g_F1[(size_t)NPAR * H1D];      // fp32, 8 MB
__device__ __half g_H2h[(size_t)NROWS * H2D];    // h2 plain fp16, 128 MB
__device__ __half g_W2T[512 * 512];              // W2^T fp16 [n][k]
__device__ __half g_W3T[256 * 512];              // W3^T fp16 [n][k]

// ---------------- mma helpers ----------------
__device__ __forceinline__ uint32_t smem_u32(const void* p) {
    uint32_t a;
    asm("{ .reg .u64 t; cvta.to.shared.u64 t, %1; cvt.u32.u64 %0, t; }" : "=r"(a) : "l"(p));
    return a;
}
__device__ __forceinline__ void ldsm4(uint32_t r[4], uint32_t addr) {
    asm volatile("ldmatrix.sync.aligned.m8n8.x4.shared.b16 {%0,%1,%2,%3}, [%4];"
                 : "=r"(r[0]), "=r"(r[1]), "=r"(r[2]), "=r"(r[3]) : "r"(addr));
}
__device__ __forceinline__ void mma_f16(float c[4], const uint32_t a[4],
                                        uint32_t b0, uint32_t b1) {
    asm volatile("mma.sync.aligned.m16n8k16.row.col.f32.f16.f16.f32 "
                 "{%0,%1,%2,%3}, {%4,%5,%6,%7}, {%8,%9}, {%0,%1,%2,%3};"
                 : "+f"(c[0]), "+f"(c[1]), "+f"(c[2]), "+f"(c[3])
                 : "r"(a[0]), "r"(a[1]), "r"(a[2]), "r"(a[3]), "r"(b0), "r"(b1));
}

// ---------------- SMEM layout ----------------
// kc=32 chunks; tile row = 32 halves = 64B, padded to 80B (16B aligned,
// 8 rows at stride 80 hit 8 distinct 16B bank groups -> conflict-free ldsm).
#define KC      32
#define NCH0    (H1D / KC)            // 16 chunks (K=512)
#define LDT     80
#define TILE_B  (128 * LDT)           // 10240
#define OFF_A   0
#define OFF_B   TILE_B
#define BUFSZ   (2 * TILE_B)          // 20480
#define OFF_W1T (2 * BUFSZ)           // 40960, 3*512 floats = 6144
#define OFF_RPS (OFF_W1T + 6144)      // 128*3 floats = 1536
#define SMEM_TOTAL (OFF_RPS + 1536)   // 48640

// ---------------- kernel 1: decoder GEMM ----------------
__global__ void k_dec(const float* __restrict__ inf, const float* __restrict__ Wd,
                      const float* __restrict__ bd, float* __restrict__ out_rp)
{
    __shared__ float s[NEIGHD];
    const int p = blockIdx.x;
    const int t = threadIdx.x;
    s[t] = inf[(size_t)p * INSTR + t];
    __syncthreads();
    if (t < 96) {
        float acc = bd[t];
#pragma unroll 8
        for (int k = 0; k < NEIGHD; ++k)
            acc = fmaf(s[k], Wd[k * 96 + t], acc);
        out_rp[(size_t)p * 96 + t] = acc;
    }
}

// ---------------- kernel 2: cluster indices ----------------
__global__ void k_cluster(float* __restrict__ out_cl)
{
    const int i = blockIdx.x * blockDim.x + threadIdx.x;
    if (i < NROWS) out_cl[i] = (float)(i >> 5);
}

// ---------------- kernel 3: F1 = features @ W1[0:256,:] + b1 (fp32 SIMT) ----
__global__ void k_f1(const float* __restrict__ inf, const float* __restrict__ W1,
                     const float* __restrict__ b1)
{
    __shared__ float As[16 * 132];
    __shared__ float Bs[16 * 128];
    const int tid  = threadIdx.x;
    const int bm   = blockIdx.x * 128;
    const int bn   = blockIdx.y * 128;
    const int arow = tid >> 2;
    const int acol = (tid & 3) * 4;
    const int brow = tid >> 5;
    const int bcol = (tid & 31) * 4;
    const int tr   = (tid >> 4) * 8;
    const int tc   = (tid & 15) * 8;

    float acc[8][8];
#pragma unroll
    for (int i = 0; i < 8; ++i)
#pragma unroll
        for (int j = 0; j < 8; ++j) acc[i][j] = 0.f;

    for (int kt = 0; kt < FEATD; kt += 16) {
#pragma unroll
        for (int s = 0; s < 2; ++s) {
            const int m = arow + s * 64;
            const float4 av = *(const float4*)&inf[(size_t)(bm + m) * INSTR + NEIGHD + kt + acol];
            As[(acol + 0) * 132 + m] = av.x;
            As[(acol + 1) * 132 + m] = av.y;
            As[(acol + 2) * 132 + m] = av.z;
            As[(acol + 3) * 132 + m] = av.w;
        }
#pragma unroll
        for (int s = 0; s < 2; ++s) {
            const int k = brow + s * 8;
            *(float4*)&Bs[k * 128 + bcol] =
                *(const float4*)&W1[(size_t)(kt + k) * H1D + bn + bcol];
        }
        __syncthreads();
#pragma unroll
        for (int k = 0; k < 16; ++k) {
            const float4 a0 = *(const float4*)&As[k * 132 + tr];
            const float4 a1 = *(const float4*)&As[k * 132 + tr + 4];
            const float4 b0 = *(const float4*)&Bs[k * 128 + tc];
            const float4 b1v = *(const float4*)&Bs[k * 128 + tc + 4];
            const float am[8] = {a0.x, a0.y, a0.z, a0.w, a1.x, a1.y, a1.z, a1.w};
            const float bnv[8] = {b0.x, b0.y, b0.z, b0.w, b1v.x, b1v.y, b1v.z, b1v.w};
#pragma unroll
            for (int i = 0; i < 8; ++i)
#pragma unroll
                for (int j = 0; j < 8; ++j)
                    acc[i][j] = fmaf(am[i], bnv[j], acc[i][j]);
        }
        __syncthreads();
    }
#pragma unroll
    for (int i = 0; i < 8; ++i) {
        const size_t row = (size_t)(bm + tr + i);
#pragma unroll
        for (int j = 0; j < 8; ++j)
            g_F1[row * H1D + bn + tc + j] = acc[i][j] + b1[bn + tc + j];
    }
}

// ---------------- weight transpose + fp16 prep ----------------
__global__ void k_prep_w2(const float* __restrict__ W2)
{
    const int idx = blockIdx.x * 256 + threadIdx.x;   // n*512 + k
    const int n = idx >> 9, k = idx & 511;
    g_W2T[idx] = __float2half(W2[(size_t)k * H2D + n]);
}
__global__ void k_prep_w3(const float* __restrict__ W3)
{
    const int idx = blockIdx.x * 256 + threadIdx.x;   // n*512 + k
    const int n = idx >> 9, k = idx & 511;
    g_W3T[idx] = __float2half(W3[(size_t)k * H3D + n]);
}

// =======================================================================
// Double-buffered mma.sync fp16 GEMM. CTA tile 128x128, K=512, kc=32.
// Single fp16 term both layers (error budget validated by RSS model).
// MODE 0: A = relu(F1[parent] + rp.W1tail) fp16, B = W2^T, out = g_H2h fp16.
// MODE 1: A = g_H2h fp16, B = W3^T, out = fp32 h.
// Pipeline: prefetch globals (c+1) -> MMA(c) -> cvt+STS(c+1) -> barrier.
// =======================================================================
template<int MODE>
__global__ void __launch_bounds__(256, 2) k_mlp_mma(
    const float* __restrict__ rp, const float* __restrict__ W1,
    const float* __restrict__ bias, float* __restrict__ outf)
{
    extern __shared__ char smem[];
    const uint32_t su = smem_u32(smem);
    const int tid  = threadIdx.x;
    const int wid  = tid >> 5;
    const int lane = tid & 31;
    const int bm   = blockIdx.x * 128;
    const int bn   = blockIdx.y * 128;

    float* w1t = (float*)(smem + OFF_W1T);
    float* rps = (float*)(smem + OFF_RPS);
    if (MODE == 0) {
        for (int i = tid; i < 3 * H1D; i += 256)
            w1t[i] = W1[(size_t)(FEATD + i / H1D) * H1D + (i % H1D)];
        for (int i = tid; i < 128 * 3; i += 256)
            rps[i] = rp[(size_t)bm * 3 + i];
    }
    __syncthreads();

    const int warpM = wid & 3;
    const int warpN = wid >> 2;
    const int prow  = tid >> 1;            // 0..127 (prep row)
    const int pc0   = (tid & 1) * 16;      // 0 or 16 (prep k offset)

    const int a_row  = warpM * 32 + (lane & 15);
    const int a_kofs = (lane >> 4) * 8;
    const int b_row  = warpN * 64 + (lane & 7) + ((lane >> 4) << 3);
    const int b_kofs = ((lane >> 3) & 1) * 8;

    const __half* Bsrc = (MODE == 0) ? g_W2T : g_W3T;

    float c[2][8][4];
#pragma unroll
    for (int i = 0; i < 2; ++i)
#pragma unroll
        for (int j = 0; j < 8; ++j)
#pragma unroll
            for (int q = 0; q < 4; ++q) c[i][j][q] = 0.f;

    // prefetch registers
    float4 pf[4];      // MODE0: F1 segment (16 floats)
    uint4  pa[2];      // MODE1: A fp16 (16 halves)
    uint4  pb[2];      // B fp16 (16 halves)

    auto fetch = [&](int ch) {
        const int kt = ch * KC;
        if (MODE == 0) {
            const float* f = &g_F1[(size_t)((bm + prow) >> 5) * H1D + kt + pc0];
#pragma unroll
            for (int q = 0; q < 4; ++q) pf[q] = *(const float4*)(f + 4 * q);
        } else {
            const __half* a = &g_H2h[(size_t)(bm + prow) * H2D + kt + pc0];
            pa[0] = *(const uint4*)a;
            pa[1] = *(const uint4*)(a + 8);
        }
        const __half* b = &Bsrc[(size_t)(bn + prow) * 512 + kt + pc0];
        pb[0] = *(const uint4*)b;
        pb[1] = *(const uint4*)(b + 8);
    };

    auto stage = [&](int ch, int buf) {
        char* base = smem + buf * BUFSZ;
        const int kt = ch * KC;
        const int ao = prow * LDT + pc0 * 2;
        if (MODE == 0) {
            const float r0 = rps[prow * 3 + 0];
            const float r1 = rps[prow * 3 + 1];
            const float r2 = rps[prow * 3 + 2];
            const float* fv = (const float*)pf;
            uint32_t uh[8];
#pragma unroll
            for (int j = 0; j < 8; ++j) {
                const int k0 = kt + pc0 + 2 * j;
                float v0 = fmaxf(fv[2*j]   + r0 * w1t[k0]   + r1 * w1t[512 + k0]   + r2 * w1t[1024 + k0],   0.f);
                float v1 = fmaxf(fv[2*j+1] + r0 * w1t[k0+1] + r1 * w1t[512 + k0+1] + r2 * w1t[1024 + k0+1], 0.f);
                const __half h0 = __float2half(v0);
                const __half h1 = __float2half(v1);
                uh[j] = (uint32_t)__half_as_ushort(h0) | ((uint32_t)__half_as_ushort(h1) << 16);
            }
            *(uint4*)(base + OFF_A + ao)      = make_uint4(uh[0], uh[1], uh[2], uh[3]);
            *(uint4*)(base + OFF_A + ao + 16) = make_uint4(uh[4], uh[5], uh[6], uh[7]);
        } else {
            *(uint4*)(base + OFF_A + ao)      = pa[0];
            *(uint4*)(base + OFF_A + ao + 16) = pa[1];
        }
        const int bo = prow * LDT + pc0 * 2;
        *(uint4*)(base + OFF_B + bo)      = pb[0];
        *(uint4*)(base + OFF_B + bo + 16) = pb[1];
    };

    auto domma = [&](int buf) {
        const uint32_t base = su + buf * BUFSZ;
#pragma unroll
        for (int ks = 0; ks < 2; ++ks) {
            const int kk = ks * 16;
            uint32_t ah[2][4];
#pragma unroll
            for (int mb = 0; mb < 2; ++mb) {
                const uint32_t aoff = (uint32_t)((a_row + mb * 16) * LDT + (kk + a_kofs) * 2);
                ldsm4(ah[mb], base + OFF_A + aoff);
            }
#pragma unroll
            for (int np = 0; np < 4; ++np) {
                uint32_t bh[4];
                const uint32_t boff = (uint32_t)((b_row + np * 16) * LDT + (kk + b_kofs) * 2);
                ldsm4(bh, base + OFF_B + boff);
#pragma unroll
                for (int mb = 0; mb < 2; ++mb) {
#pragma unroll
                    for (int ns = 0; ns < 2; ++ns) {
                        float* cc = c[mb][np * 2 + ns];
                        mma_f16(cc, ah[mb], bh[2 * ns], bh[2 * ns + 1]);
                    }
                }
            }
        }
    };

    // -------- pipeline --------
    fetch(0);
    stage(0, 0);
    __syncthreads();
#pragma unroll 1
    for (int ch = 0; ch < NCH0; ++ch) {
        if (ch + 1 < NCH0) fetch(ch + 1);
        domma(ch & 1);
        if (ch + 1 < NCH0) stage(ch + 1, (ch + 1) & 1);
        __syncthreads();
    }

    // -------- epilogue --------
    const int g   = lane >> 2;
    const int tig = lane & 3;
#pragma unroll
    for (int mb = 0; mb < 2; ++mb) {
#pragma unroll
        for (int nb = 0; nb < 8; ++nb) {
            const int col = bn + warpN * 64 + nb * 8 + tig * 2;
            const float bz0 = bias[col], bz1 = bias[col + 1];
            const int r0 = bm + warpM * 32 + mb * 16 + g;
            const float* cc = c[mb][nb];
#pragma unroll
            for (int half = 0; half < 2; ++half) {
                const int r = r0 + half * 8;
                const float h0 = fmaxf(cc[2 * half + 0] + bz0, 0.f);
                const float h1 = fmaxf(cc[2 * half + 1] + bz1, 0.f);
                if (MODE == 0) {
                    __half2 hv = __halves2half2(__float2half(h0), __float2half(h1));
                    *(__half2*)&g_H2h[(size_t)r * H2D + col] = hv;
                } else {
                    *(float2*)&outf[(size_t)r * H3D + col] = make_float2(h0, h1);
                }
            }
        }
    }
}

// ---------------- launch ----------------
extern "C" void kernel_launch(void* const* d_in, const int* in_sizes, int n_in,
                              void* d_out, int out_size)
{
    const float* inf = (const float*)d_in[0];
    const float* Wd  = (const float*)d_in[1];
    const float* bd  = (const float*)d_in[2];
    const float* W1  = (const float*)d_in[3];
    const float* b1  = (const float*)d_in[4];
    const float* W2  = (const float*)d_in[5];
    const float* b2  = (const float*)d_in[6];
    const float* W3  = (const float*)d_in[7];
    const float* b3  = (const float*)d_in[8];
    float* out = (float*)d_out;

    cudaFuncSetAttribute(k_mlp_mma<0>, cudaFuncAttributeMaxDynamicSharedMemorySize, SMEM_TOTAL);
    cudaFuncSetAttribute(k_mlp_mma<1>, cudaFuncAttributeMaxDynamicSharedMemorySize, SMEM_TOTAL);

    k_dec<<<NPAR, 128>>>(inf, Wd, bd, out + RP_OFF);
    k_cluster<<<NROWS / 256, 256>>>(out + CL_OFF);
    k_prep_w2<<<512 * 512 / 256, 256>>>(W2);
    k_prep_w3<<<256 * 512 / 256, 256>>>(W3);
    k_f1<<<dim3(NPAR / 128, H1D / 128), 256>>>(inf, W1, b1);
    k_mlp_mma<0><<<dim3(NROWS / 128, H2D / 128), 256, SMEM_TOTAL>>>(out + RP_OFF, W1, b2, nullptr);
    k_mlp_mma<1><<<dim3(NROWS / 128, H3D / 128), 256, SMEM_TOTAL>>>(nullptr, nullptr, b3, out + H_OFF);
}